// round 3
// baseline (speedup 1.0000x reference)
#include <cuda_runtime.h>
#include <cuda_bf16.h>
#include <math.h>

// ---------------- scratch (no allocation allowed; use __device__ globals) ----
#define B 4096
#define LATENT 512
#define H 8
#define D 64
#define KVB_N (H * (2 * D + 1))   // 1032

__device__ float g_h[B * LATENT];      // post-GEMM1 / post-LN
__device__ float g_h2[B * LATENT];     // post-GEMM2
__device__ float g_kvb[B * KVB_N];     // post-GEMM3

// packed f32x2 FMA: d = a*b + d (componentwise on 2 floats in a 64-bit reg)
#define FMA2(d, a, b) \
    asm("fma.rn.f32x2 %0, %1, %2, %0;" : "+l"(d) : "l"(a), "l"(b))

__device__ __forceinline__ float lo32(unsigned long long v) {
    return __uint_as_float((unsigned)v);
}
__device__ __forceinline__ float hi32(unsigned long long v) {
    return __uint_as_float((unsigned)(v >> 32));
}

// ---------------- GEMM: C[M,N] = A[M,K] @ Bmat[K,N] + bias ------------------
// CONCAT: A is concat([A0 (M,512), A1 (M,512)]) along K (K=1024)
// 128x128 block tile, BK=16, 256 threads, 8x8 per-thread microtile,
// f32x2 packed accumulation (acc pairs along M; B duplicated in smem).
#define BM 128
#define BN 128
#define BK 16
#define BROW 320   // Bs2 row: 16 groups * (16 data + 4 pad) floats

template <bool CONCAT>
__global__ __launch_bounds__(256, 2) void gemm_f32x2_kernel(
    const float* __restrict__ A0, const float* __restrict__ A1,
    const float* __restrict__ Bmat, const float* __restrict__ bias,
    float* __restrict__ C, int M, int N, int K)
{
    __shared__ float As[BK][BM];        // 8 KB
    __shared__ float Bs2[BK][BROW];     // 20 KB (duplicated + padded)

    int t = threadIdx.x;

    // ---- staging ids ----
    int am = t >> 1;                 // 0..127 (A row)
    int ak = (t & 1) * 8;            // 0 or 8 (K chunk)
    int bk = t >> 4;                 // 0..15 (B k-row)
    int bg = t & 15;                 // 0..15 (B 8-col group)
    const int gmA = blockIdx.y * BM + am;
    const int gnB = blockIdx.x * BN + bg * 8;

    // ---- compute ids: warp 8(lx: N) x 4(ly: M); block = 4(wy) x 2(wx) warps
    int w = t >> 5, l = t & 31;
    int lx = l & 7, ly = l >> 3;
    int wx = w & 1, wy = w >> 1;
    int m_base = wy * 32 + ly * 8;               // 0..120
    int g      = wx * 8 + lx;                    // 0..15
    int row0 = blockIdx.y * BM + m_base;
    int col0 = blockIdx.x * BN + g * 8;

    unsigned long long acc[4][8] = {};           // [m-pair][n]

    float4 pa0, pa1, pb0, pb1;

    auto loadA = [&](int k0) {
        int gk = k0 + ak;
        const float* ap;
        if (CONCAT) {
            ap = (gk < 512) ? (A0 + (size_t)gmA * 512 + gk)
                            : (A1 + (size_t)gmA * 512 + (gk - 512));
        } else {
            ap = A0 + (size_t)gmA * K + gk;
        }
        pa0 = *(const float4*)ap;
        pa1 = *(const float4*)(ap + 4);
    };
    auto loadB = [&](int k0) {
        pb0 = make_float4(0.f, 0.f, 0.f, 0.f);
        pb1 = pb0;
        const float* bp = Bmat + (size_t)(k0 + bk) * N + gnB;
        if (gnB + 8 <= N) {
            pb0 = *(const float4*)bp;
            pb1 = *(const float4*)(bp + 4);
        } else if (gnB + 4 <= N) {
            pb0 = *(const float4*)bp;
        }
    };
    auto stage = [&]() {
        As[ak + 0][am] = pa0.x;  As[ak + 1][am] = pa0.y;
        As[ak + 2][am] = pa0.z;  As[ak + 3][am] = pa0.w;
        As[ak + 4][am] = pa1.x;  As[ak + 5][am] = pa1.y;
        As[ak + 6][am] = pa1.z;  As[ak + 7][am] = pa1.w;
        float* dst = &Bs2[bk][bg * 20];
        ((float4*)dst)[0] = make_float4(pb0.x, pb0.x, pb0.y, pb0.y);
        ((float4*)dst)[1] = make_float4(pb0.z, pb0.z, pb0.w, pb0.w);
        ((float4*)dst)[2] = make_float4(pb1.x, pb1.x, pb1.y, pb1.y);
        ((float4*)dst)[3] = make_float4(pb1.z, pb1.z, pb1.w, pb1.w);
    };

    loadA(0); loadB(0);

    for (int k0 = 0; k0 < K; k0 += BK) {
        stage();
        __syncthreads();
        if (k0 + BK < K) { loadA(k0 + BK); loadB(k0 + BK); }

        #pragma unroll
        for (int kk = 0; kk < BK; kk++) {
            // A pairs: 4 x {m, m+1}
            const ulonglong2* ap = (const ulonglong2*)&As[kk][m_base];
            ulonglong2 A01 = ap[0], A23 = ap[1];
            unsigned long long a[4] = {A01.x, A01.y, A23.x, A23.y};
            // B dup pairs: 8 x {n, n}
            const ulonglong2* bp = (const ulonglong2*)&Bs2[kk][g * 20];
            ulonglong2 B01 = bp[0], B23 = bp[1], B45 = bp[2], B67 = bp[3];
            unsigned long long b[8] = {B01.x, B01.y, B23.x, B23.y,
                                       B45.x, B45.y, B67.x, B67.y};
            #pragma unroll
            for (int p = 0; p < 4; p++)
                #pragma unroll
                for (int j = 0; j < 8; j++)
                    FMA2(acc[p][j], a[p], b[j]);
        }
        __syncthreads();
    }

    // ---- epilogue: add bias, store ----
    if (col0 < N) {                           // N % 8 == 0 -> full 8-col group
        float4 bz0 = *(const float4*)(bias + col0);
        float4 bz1 = *(const float4*)(bias + col0 + 4);
        float bb[8] = {bz0.x, bz0.y, bz0.z, bz0.w, bz1.x, bz1.y, bz1.z, bz1.w};
        #pragma unroll
        for (int p = 0; p < 4; p++) {
            float* c0 = C + (size_t)(row0 + 2 * p) * N + col0;
            float* c1 = c0 + N;
            float r0[8], r1[8];
            #pragma unroll
            for (int j = 0; j < 8; j++) {
                r0[j] = lo32(acc[p][j]) + bb[j];
                r1[j] = hi32(acc[p][j]) + bb[j];
            }
            ((float4*)c0)[0] = make_float4(r0[0], r0[1], r0[2], r0[3]);
            ((float4*)c0)[1] = make_float4(r0[4], r0[5], r0[6], r0[7]);
            ((float4*)c1)[0] = make_float4(r1[0], r1[1], r1[2], r1[3]);
            ((float4*)c1)[1] = make_float4(r1[4], r1[5], r1[6], r1[7]);
        }
    }
}

// ---------------- LayerNorm over last dim (512), in place -------------------
__global__ __launch_bounds__(128) void ln_kernel(
    float* __restrict__ h, const float* __restrict__ g, const float* __restrict__ b)
{
    int row = blockIdx.x;
    float4* hp = (float4*)(h + (size_t)row * LATENT);
    int t = threadIdx.x;              // 128 threads, 1 float4 each
    float4 v = hp[t];
    float s  = v.x + v.y + v.z + v.w;
    float sq = v.x * v.x + v.y * v.y + v.z * v.z + v.w * v.w;

    #pragma unroll
    for (int o = 16; o; o >>= 1) {
        s  += __shfl_xor_sync(0xffffffffu, s, o);
        sq += __shfl_xor_sync(0xffffffffu, sq, o);
    }
    __shared__ float rs[4], rq[4];
    int lane = t & 31, wid = t >> 5;
    if (lane == 0) { rs[wid] = s; rq[wid] = sq; }
    __syncthreads();
    float S  = rs[0] + rs[1] + rs[2] + rs[3];
    float SQ = rq[0] + rq[1] + rq[2] + rq[3];
    float mu  = S * (1.0f / LATENT);
    float var = SQ * (1.0f / LATENT) - mu * mu;
    float r = rsqrtf(var + 1e-5f);

    float4 gv = ((const float4*)g)[t];
    float4 bv = ((const float4*)b)[t];
    v.x = (v.x - mu) * r * gv.x + bv.x;
    v.y = (v.y - mu) * r * gv.y + bv.y;
    v.z = (v.z - mu) * r * gv.z + bv.z;
    v.w = (v.w - mu) * r * gv.w + bv.w;
    hp[t] = v;
}

// ---------------- Oja update: one block per (b,h) ---------------------------
// kvb row layout per b: H * 129; per head: [ks(64), vs(64), lr(1)]
__global__ __launch_bounds__(128) void oja_kernel(
    const float* __restrict__ kvb, const float* __restrict__ W, float* __restrict__ out)
{
    int bh = blockIdx.x;                       // b*8 + h
    const float* w = W   + (size_t)bh * (D * D);
    float*       o = out + (size_t)bh * (D * D);
    const float* kv = kvb + (size_t)(bh >> 3) * KVB_N + (size_t)(bh & 7) * (2 * D + 1);

    __shared__ float Ws[D * D];     // 16 KB
    __shared__ float vs[D], ksc[D], logit[D];
    __shared__ float lr_raw;

    int t = threadIdx.x;            // 128 threads

    #pragma unroll
    for (int i = t; i < (D * D) / 4; i += 128)
        ((float4*)Ws)[i] = ((const float4*)w)[i];
    if (t < D)     vs[t] = tanhf(kv[D + t]);
    if (t == 127)  lr_raw = kv[2 * D];
    __syncthreads();

    if (t < D) {
        float acc = 0.f;
        #pragma unroll 16
        for (int d = 0; d < D; d++)
            acc = fmaf(Ws[d * D + t], vs[d], acc);
        logit[t] = kv[t] - acc;
    }
    __syncthreads();

    // softmax over 64 (computed redundantly by all threads; cheap)
    float m = -1e30f;
    #pragma unroll
    for (int e = 0; e < D; e++) m = fmaxf(m, logit[e]);
    float ssum = 0.f;
    #pragma unroll
    for (int e = 0; e < D; e++) ssum += expf(logit[e] - m);
    float inv = 1.0f / ssum;
    float lr  = 1.0f / (1.0f + expf(-lr_raw));
    if (t < D) ksc[t] = expf(logit[t] - m) * inv * lr;
    __syncthreads();

    // out[d][e] = vs[d]*ksc[e] + W[d][e], vectorized
    #pragma unroll
    for (int i = t; i < (D * D) / 4; i += 128) {
        float4 wv = ((const float4*)Ws)[i];
        int d  = i >> 4;          // (i*4)/64
        int e0 = (i * 4) & (D - 1);
        float vd = vs[d];
        float4 r;
        r.x = fmaf(vd, ksc[e0 + 0], wv.x);
        r.y = fmaf(vd, ksc[e0 + 1], wv.y);
        r.z = fmaf(vd, ksc[e0 + 2], wv.z);
        r.w = fmaf(vd, ksc[e0 + 3], wv.w);
        ((float4*)o)[i] = r;
    }
}

// ---------------- launch ----------------------------------------------------
extern "C" void kernel_launch(void* const* d_in, const int* in_sizes, int n_in,
                              void* d_out, int out_size)
{
    const float* x     = (const float*)d_in[0];
    const float* z     = (const float*)d_in[1];
    const float* W     = (const float*)d_in[2];
    const float* ip_w  = (const float*)d_in[3];
    const float* ip_b  = (const float*)d_in[4];
    const float* ln_g  = (const float*)d_in[5];
    const float* ln_b  = (const float*)d_in[6];
    const float* mg_w  = (const float*)d_in[7];
    const float* mg_b  = (const float*)d_in[8];
    const float* kvb_w = (const float*)d_in[9];
    const float* kvb_b = (const float*)d_in[10];
    float* out = (float*)d_out;

    float *hP, *h2P, *kvbP;
    cudaGetSymbolAddress((void**)&hP,   g_h);
    cudaGetSymbolAddress((void**)&h2P,  g_h2);
    cudaGetSymbolAddress((void**)&kvbP, g_kvb);

    // GEMM1: h = x @ ip_w + ip_b   (M=4096, N=512, K=512)
    gemm_f32x2_kernel<false><<<dim3(512 / BN, B / BM), 256>>>(
        x, nullptr, ip_w, ip_b, hP, B, 512, 512);

    // LayerNorm in place
    ln_kernel<<<B, 128>>>(hP, ln_g, ln_b);

    // GEMM2: h2 = [h, z] @ mg_w + mg_b   (M=4096, N=512, K=1024)
    gemm_f32x2_kernel<true><<<dim3(512 / BN, B / BM), 256>>>(
        hP, z, mg_w, mg_b, h2P, B, 512, 1024);

    // GEMM3: kvb = h2 @ kvb_w + kvb_b   (M=4096, N=1032, K=512)
    gemm_f32x2_kernel<false><<<dim3((KVB_N + BN - 1) / BN, B / BM), 256>>>(
        h2P, nullptr, kvb_w, kvb_b, kvbP, B, KVB_N, 512);

    // Oja update: one block per (b, h)
    oja_kernel<<<B * H, 128>>>(kvbP, W, out);
}

// round 5
// speedup vs baseline: 1.4657x; 1.4657x over previous
#include <cuda_runtime.h>
#include <cuda_bf16.h>
#include <math.h>
#include <stdint.h>

#define B 4096
#define LATENT 512
#define H 8
#define D 64
#define KVB_N (H * (2 * D + 1))   // 1032

// ---------------- scratch (device globals; no allocation allowed) -----------
__device__ float g_h[B * LATENT];                 // post-GEMM1 (fp32, for LN)
__device__ float g_kvb[B * KVB_N];                // post-GEMM3 (fp32, for oja)
__device__ __nv_bfloat16 g_xhi[B * 512],  g_xlo[B * 512];
__device__ __nv_bfloat16 g_zhi[B * 512],  g_zlo[B * 512];
__device__ __nv_bfloat16 g_hhi[B * 512],  g_hlo[B * 512];
__device__ __nv_bfloat16 g_h2hi[B * 512], g_h2lo[B * 512];
__device__ __nv_bfloat16 g_ipwT_hi[512 * 512],    g_ipwT_lo[512 * 512];     // [N=512,K=512]
__device__ __nv_bfloat16 g_mgwT_hi[512 * 1024],   g_mgwT_lo[512 * 1024];    // [N=512,K=1024]
__device__ __nv_bfloat16 g_kvbwT_hi[KVB_N * 512], g_kvbwT_lo[KVB_N * 512];  // [N=1032,K=512]

// ---------------- mma helpers ------------------------------------------------
__device__ __forceinline__ uint32_t smem_u32(const void* p) {
    uint32_t a;
    asm("{ .reg .u64 t; cvta.to.shared.u64 t, %1; cvt.u32.u64 %0, t; }"
        : "=r"(a) : "l"(p));
    return a;
}
__device__ __forceinline__ void ldm_x4(uint32_t (&r)[4], uint32_t addr) {
    asm volatile("ldmatrix.sync.aligned.m8n8.x4.shared.b16 {%0,%1,%2,%3}, [%4];"
        : "=r"(r[0]), "=r"(r[1]), "=r"(r[2]), "=r"(r[3]) : "r"(addr));
}
__device__ __forceinline__ void mma16816(float* c, const uint32_t* a,
                                         uint32_t b0, uint32_t b1) {
    asm volatile("mma.sync.aligned.m16n8k16.row.col.f32.bf16.bf16.f32 "
        "{%0,%1,%2,%3}, {%4,%5,%6,%7}, {%8,%9}, {%0,%1,%2,%3};"
        : "+f"(c[0]), "+f"(c[1]), "+f"(c[2]), "+f"(c[3])
        : "r"(a[0]), "r"(a[1]), "r"(a[2]), "r"(a[3]), "r"(b0), "r"(b1));
}
__device__ __forceinline__ void split1(float v, __nv_bfloat16& h, __nv_bfloat16& l) {
    h = __float2bfloat16(v);
    l = __float2bfloat16(v - __bfloat162float(h));
}

// ---------------- prep kernels -----------------------------------------------
__global__ __launch_bounds__(256) void split_kernel(
    const float* __restrict__ src, __nv_bfloat16* __restrict__ hi,
    __nv_bfloat16* __restrict__ lo, int n4)
{
    int i = blockIdx.x * 256 + threadIdx.x;
    if (i >= n4) return;
    float4 v = ((const float4*)src)[i];
    __nv_bfloat16 h0,l0,h1,l1,h2,l2,h3,l3;
    split1(v.x,h0,l0); split1(v.y,h1,l1); split1(v.z,h2,l2); split1(v.w,h3,l3);
    __nv_bfloat162 ph0, ph1, pl0, pl1;
    ph0.x=h0; ph0.y=h1; ph1.x=h2; ph1.y=h3;
    pl0.x=l0; pl0.y=l1; pl1.x=l2; pl1.y=l3;
    ((__nv_bfloat162*)hi)[i*2]   = ph0; ((__nv_bfloat162*)hi)[i*2+1] = ph1;
    ((__nv_bfloat162*)lo)[i*2]   = pl0; ((__nv_bfloat162*)lo)[i*2+1] = pl1;
}

// transpose + split: src [K,N] fp32 -> hi/lo [N,K] bf16
__global__ __launch_bounds__(256) void tsplit_kernel(
    const float* __restrict__ src, __nv_bfloat16* __restrict__ hi,
    __nv_bfloat16* __restrict__ lo, int K, int N)
{
    int id = blockIdx.x * 256 + threadIdx.x;
    if (id >= K * N) return;
    int k = id / N, n = id - k * N;
    __nv_bfloat16 h, l; split1(src[id], h, l);
    hi[(size_t)n * K + k] = h;
    lo[(size_t)n * K + k] = l;
}

// ---------------- mma.sync GEMM ----------------------------------------------
// C[M=4096,N] = A[M,K] @ Bw^T + bias.  A pre-split bf16 (row stride 512; two
// arrays when CONCAT), Bw pre-transposed+split [N,K] bf16 (k contiguous).
// 128x128 block tile, BK=32, 256 threads = 8 warps (2 M x 4 N), 64x32/warp.
// Split precision: acc += Ahi*Bhi + Ahi*Blo + Alo*Bhi.
#define PAD 40   // bf16 elems per smem row (80 B) -> conflict-free ldmatrix

template <bool CONCAT, bool SPLIT_OUT>
__global__ __launch_bounds__(256) void gemm_mma(
    const __nv_bfloat16* __restrict__ A0hi, const __nv_bfloat16* __restrict__ A0lo,
    const __nv_bfloat16* __restrict__ A1hi, const __nv_bfloat16* __restrict__ A1lo,
    const __nv_bfloat16* __restrict__ Bwhi, const __nv_bfloat16* __restrict__ Bwlo,
    const float* __restrict__ bias,
    float* __restrict__ Cf,
    __nv_bfloat16* __restrict__ Chi, __nv_bfloat16* __restrict__ Clo,
    int N, int K)
{
    __shared__ __nv_bfloat16 As_hi[128][PAD], As_lo[128][PAD];
    __shared__ __nv_bfloat16 Bs_hi[128][PAD], Bs_lo[128][PAD];

    int t = threadIdx.x;
    int wid = t >> 5, lane = t & 31;
    int wy = wid & 1, wx = wid >> 1;               // 2 x 4 warps
    int row0 = blockIdx.y * 128;
    int col0 = blockIdx.x * 128;

    // staging mapping: u = t + 256*i (i=0,1); row = u>>2, 16B chunk = u&3
    int srow = t >> 2;            // 0..63 (i=0), +64 (i=1)
    int sc16 = t & 3;             // k-chunk of 8 bf16

    float acc[4][4][4] = {};      // [mt][nt][4]

    uint4 pAh[2], pAl[2], pBh[2], pBl[2];

    auto loadg = [&](int ch) {
        int k0 = ch * 32;
        const __nv_bfloat16 *Ah, *Al; int ka;
        if (CONCAT && k0 >= 512) { Ah = A1hi; Al = A1lo; ka = k0 - 512; }
        else                     { Ah = A0hi; Al = A0lo; ka = k0; }
        #pragma unroll
        for (int i = 0; i < 2; i++) {
            int r = srow + i * 64;
            int ko = ka + sc16 * 8;
            pAh[i] = *(const uint4*)(Ah + (size_t)(row0 + r) * 512 + ko);
            pAl[i] = *(const uint4*)(Al + (size_t)(row0 + r) * 512 + ko);
            int gn = col0 + r;
            uint4 bh = make_uint4(0,0,0,0), bl = bh;
            if (gn < N) {
                bh = *(const uint4*)(Bwhi + (size_t)gn * K + k0 + sc16 * 8);
                bl = *(const uint4*)(Bwlo + (size_t)gn * K + k0 + sc16 * 8);
            }
            pBh[i] = bh; pBl[i] = bl;
        }
    };
    auto stage = [&]() {
        #pragma unroll
        for (int i = 0; i < 2; i++) {
            int r = srow + i * 64;
            *(uint4*)&As_hi[r][sc16 * 8] = pAh[i];
            *(uint4*)&As_lo[r][sc16 * 8] = pAl[i];
            *(uint4*)&Bs_hi[r][sc16 * 8] = pBh[i];
            *(uint4*)&Bs_lo[r][sc16 * 8] = pBl[i];
        }
    };

    uint32_t sAh = smem_u32(As_hi), sAl = smem_u32(As_lo);
    uint32_t sBh = smem_u32(Bs_hi), sBl = smem_u32(Bs_lo);

    // ldmatrix lane offsets
    int a_row_off = (lane & 7) + ((lane & 8) ? 8 : 0);
    int a_ch_off  = (lane & 16) ? 1 : 0;
    int b_row_off = (lane & 7) + ((lane & 16) ? 8 : 0);
    int b_ch_off  = (lane & 8) ? 1 : 0;

    int nch = K / 32;
    loadg(0);

    for (int ch = 0; ch < nch; ch++) {
        stage();
        __syncthreads();
        if (ch + 1 < nch) loadg(ch + 1);

        #pragma unroll
        for (int ks = 0; ks < 2; ks++) {
            uint32_t ah[4][4], al[4][4], bh[2][4], bl[2][4];
            int ac = (ks * 2 + a_ch_off) * 8;   // bf16 offset of 16B chunk
            int bc = (ks * 2 + b_ch_off) * 8;
            #pragma unroll
            for (int mt = 0; mt < 4; mt++) {
                int r = wy * 64 + mt * 16 + a_row_off;
                uint32_t off = (uint32_t)(r * PAD + ac) * 2;
                ldm_x4(ah[mt], sAh + off);
                ldm_x4(al[mt], sAl + off);
            }
            #pragma unroll
            for (int nt2 = 0; nt2 < 2; nt2++) {
                int r = wx * 32 + nt2 * 16 + b_row_off;
                uint32_t off = (uint32_t)(r * PAD + bc) * 2;
                ldm_x4(bh[nt2], sBh + off);
                ldm_x4(bl[nt2], sBl + off);
            }
            #pragma unroll
            for (int mt = 0; mt < 4; mt++)
                #pragma unroll
                for (int nt = 0; nt < 4; nt++) {
                    uint32_t bh0 = bh[nt >> 1][(nt & 1) * 2];
                    uint32_t bh1 = bh[nt >> 1][(nt & 1) * 2 + 1];
                    uint32_t bl0 = bl[nt >> 1][(nt & 1) * 2];
                    uint32_t bl1 = bl[nt >> 1][(nt & 1) * 2 + 1];
                    mma16816(acc[mt][nt], ah[mt], bh0, bh1);
                    mma16816(acc[mt][nt], ah[mt], bl0, bl1);
                    mma16816(acc[mt][nt], al[mt], bh0, bh1);
                }
        }
        __syncthreads();
    }

    // ---- epilogue ----
    int qr = lane >> 2;            // 0..7
    int qc = (lane & 3) * 2;
    #pragma unroll
    for (int mt = 0; mt < 4; mt++) {
        #pragma unroll
        for (int nt = 0; nt < 4; nt++) {
            int gm = row0 + wy * 64 + mt * 16 + qr;
            int gc = col0 + wx * 32 + nt * 8 + qc;
            float* c = acc[mt][nt];
            if (gc < N) {
                float b0 = bias[gc], b1 = bias[gc + 1];
                if (!SPLIT_OUT) {
                    float2 r01 = make_float2(c[0] + b0, c[1] + b1);
                    float2 r23 = make_float2(c[2] + b0, c[3] + b1);
                    *(float2*)(Cf + (size_t)gm * N + gc)       = r01;
                    *(float2*)(Cf + (size_t)(gm + 8) * N + gc) = r23;
                } else {
                    float v0 = c[0] + b0, v1 = c[1] + b1;
                    float v2 = c[2] + b0, v3 = c[3] + b1;
                    __nv_bfloat16 h0,l0,h1,l1,h2,l2,h3,l3;
                    split1(v0,h0,l0); split1(v1,h1,l1);
                    split1(v2,h2,l2); split1(v3,h3,l3);
                    __nv_bfloat162 p;
                    p.x=h0; p.y=h1; *(__nv_bfloat162*)(Chi + (size_t)gm * 512 + gc) = p;
                    p.x=l0; p.y=l1; *(__nv_bfloat162*)(Clo + (size_t)gm * 512 + gc) = p;
                    p.x=h2; p.y=h3; *(__nv_bfloat162*)(Chi + (size_t)(gm + 8) * 512 + gc) = p;
                    p.x=l2; p.y=l3; *(__nv_bfloat162*)(Clo + (size_t)(gm + 8) * 512 + gc) = p;
                }
            }
        }
    }
}

// ---------------- LayerNorm (512) -> split bf16 ------------------------------
__global__ __launch_bounds__(128) void ln_split_kernel(
    const float* __restrict__ h, const float* __restrict__ g, const float* __restrict__ b,
    __nv_bfloat16* __restrict__ ohi, __nv_bfloat16* __restrict__ olo)
{
    int row = blockIdx.x;
    const float4* hp = (const float4*)(h + (size_t)row * LATENT);
    int t = threadIdx.x;
    float4 v = hp[t];
    float s  = v.x + v.y + v.z + v.w;
    float sq = v.x*v.x + v.y*v.y + v.z*v.z + v.w*v.w;
    #pragma unroll
    for (int o = 16; o; o >>= 1) {
        s  += __shfl_xor_sync(0xffffffffu, s, o);
        sq += __shfl_xor_sync(0xffffffffu, sq, o);
    }
    __shared__ float rs[4], rq[4];
    int lane = t & 31, wid = t >> 5;
    if (lane == 0) { rs[wid] = s; rq[wid] = sq; }
    __syncthreads();
    float S  = rs[0]+rs[1]+rs[2]+rs[3];
    float SQ = rq[0]+rq[1]+rq[2]+rq[3];
    float mu  = S * (1.0f / LATENT);
    float var = SQ * (1.0f / LATENT) - mu * mu;
    float rr  = rsqrtf(var + 1e-5f);
    float4 gv = ((const float4*)g)[t];
    float4 bv = ((const float4*)b)[t];
    float o0 = (v.x-mu)*rr*gv.x + bv.x;
    float o1 = (v.y-mu)*rr*gv.y + bv.y;
    float o2 = (v.z-mu)*rr*gv.z + bv.z;
    float o3 = (v.w-mu)*rr*gv.w + bv.w;
    __nv_bfloat16 h0,l0,h1,l1,h2,l2,h3,l3;
    split1(o0,h0,l0); split1(o1,h1,l1); split1(o2,h2,l2); split1(o3,h3,l3);
    __nv_bfloat162 ph0,ph1,pl0,pl1;
    ph0.x=h0; ph0.y=h1; ph1.x=h2; ph1.y=h3;
    pl0.x=l0; pl0.y=l1; pl1.x=l2; pl1.y=l3;
    size_t base = (size_t)row * LATENT + t * 4;
    *(__nv_bfloat162*)(ohi + base)     = ph0;
    *(__nv_bfloat162*)(ohi + base + 2) = ph1;
    *(__nv_bfloat162*)(olo + base)     = pl0;
    *(__nv_bfloat162*)(olo + base + 2) = pl1;
}

// ---------------- Oja update: one block per (b,h) ----------------------------
__global__ __launch_bounds__(128) void oja_kernel(
    const float* __restrict__ kvb, const float* __restrict__ W, float* __restrict__ out)
{
    int bh = blockIdx.x;
    const float* w = W   + (size_t)bh * (D * D);
    float*       o = out + (size_t)bh * (D * D);
    const float* kv = kvb + (size_t)(bh >> 3) * KVB_N + (size_t)(bh & 7) * (2 * D + 1);

    __shared__ float Ws[D * D];
    __shared__ float vs[D], ksc[D], logit[D];
    __shared__ float lr_raw;
    int t = threadIdx.x;

    #pragma unroll
    for (int i = t; i < (D * D) / 4; i += 128)
        ((float4*)Ws)[i] = ((const float4*)w)[i];
    if (t < D)    vs[t] = tanhf(kv[D + t]);
    if (t == 127) lr_raw = kv[2 * D];
    __syncthreads();

    if (t < D) {
        float acc = 0.f;
        #pragma unroll 16
        for (int d = 0; d < D; d++)
            acc = fmaf(Ws[d * D + t], vs[d], acc);
        logit[t] = kv[t] - acc;
    }
    __syncthreads();

    float m = -1e30f;
    #pragma unroll
    for (int e = 0; e < D; e++) m = fmaxf(m, logit[e]);
    float ssum = 0.f;
    #pragma unroll
    for (int e = 0; e < D; e++) ssum += expf(logit[e] - m);
    float inv = 1.0f / ssum;
    float lr  = 1.0f / (1.0f + expf(-lr_raw));
    if (t < D) ksc[t] = expf(logit[t] - m) * inv * lr;
    __syncthreads();

    #pragma unroll
    for (int i = t; i < (D * D) / 4; i += 128) {
        float4 wv = ((const float4*)Ws)[i];
        int d  = i >> 4;
        int e0 = (i * 4) & (D - 1);
        float vd = vs[d];
        float4 r;
        r.x = fmaf(vd, ksc[e0 + 0], wv.x);
        r.y = fmaf(vd, ksc[e0 + 1], wv.y);
        r.z = fmaf(vd, ksc[e0 + 2], wv.z);
        r.w = fmaf(vd, ksc[e0 + 3], wv.w);
        ((float4*)o)[i] = r;
    }
}

// ---------------- launch -----------------------------------------------------
extern "C" void kernel_launch(void* const* d_in, const int* in_sizes, int n_in,
                              void* d_out, int out_size)
{
    const float* x     = (const float*)d_in[0];
    const float* z     = (const float*)d_in[1];
    const float* W     = (const float*)d_in[2];
    const float* ip_w  = (const float*)d_in[3];
    const float* ip_b  = (const float*)d_in[4];
    const float* ln_g  = (const float*)d_in[5];
    const float* ln_b  = (const float*)d_in[6];
    const float* mg_w  = (const float*)d_in[7];
    const float* mg_b  = (const float*)d_in[8];
    const float* kvb_w = (const float*)d_in[9];
    const float* kvb_b = (const float*)d_in[10];
    float* out = (float*)d_out;

    float *hP, *kvbP;
    __nv_bfloat16 *xhi,*xlo,*zhi,*zlo,*hhi,*hlo,*h2hi,*h2lo;
    __nv_bfloat16 *ipwhi,*ipwlo,*mgwhi,*mgwlo,*kvbwhi,*kvbwlo;
    cudaGetSymbolAddress((void**)&hP,    g_h);
    cudaGetSymbolAddress((void**)&kvbP,  g_kvb);
    cudaGetSymbolAddress((void**)&xhi,   g_xhi);   cudaGetSymbolAddress((void**)&xlo,   g_xlo);
    cudaGetSymbolAddress((void**)&zhi,   g_zhi);   cudaGetSymbolAddress((void**)&zlo,   g_zlo);
    cudaGetSymbolAddress((void**)&hhi,   g_hhi);   cudaGetSymbolAddress((void**)&hlo,   g_hlo);
    cudaGetSymbolAddress((void**)&h2hi,  g_h2hi);  cudaGetSymbolAddress((void**)&h2lo,  g_h2lo);
    cudaGetSymbolAddress((void**)&ipwhi, g_ipwT_hi); cudaGetSymbolAddress((void**)&ipwlo, g_ipwT_lo);
    cudaGetSymbolAddress((void**)&mgwhi, g_mgwT_hi); cudaGetSymbolAddress((void**)&mgwlo, g_mgwT_lo);
    cudaGetSymbolAddress((void**)&kvbwhi,g_kvbwT_hi);cudaGetSymbolAddress((void**)&kvbwlo,g_kvbwT_lo);

    // prep: split activations, transpose+split weights
    split_kernel<<<(B*512/4 + 255)/256, 256>>>(x, xhi, xlo, B*512/4);
    split_kernel<<<(B*512/4 + 255)/256, 256>>>(z, zhi, zlo, B*512/4);
    tsplit_kernel<<<(512*512   + 255)/256, 256>>>(ip_w,  ipwhi,  ipwlo,  512, 512);
    tsplit_kernel<<<(1024*512  + 255)/256, 256>>>(mg_w,  mgwhi,  mgwlo,  1024, 512);
    tsplit_kernel<<<(512*KVB_N + 255)/256, 256>>>(kvb_w, kvbwhi, kvbwlo, 512, KVB_N);

    // GEMM1: h = x @ ip_w + ip_b   (N=512, K=512) -> fp32
    gemm_mma<false,false><<<dim3(4, 32), 256>>>(
        xhi, xlo, nullptr, nullptr, ipwhi, ipwlo, ip_b,
        hP, nullptr, nullptr, 512, 512);

    // LN -> split bf16
    ln_split_kernel<<<B, 128>>>(hP, ln_g, ln_b, hhi, hlo);

    // GEMM2: h2 = [h, z] @ mg_w + mg_b  (N=512, K=1024) -> split bf16
    gemm_mma<true,true><<<dim3(4, 32), 256>>>(
        hhi, hlo, zhi, zlo, mgwhi, mgwlo, mg_b,
        nullptr, h2hi, h2lo, 512, 1024);

    // GEMM3: kvb = h2 @ kvb_w + kvb_b  (N=1032, K=512) -> fp32
    gemm_mma<false,false><<<dim3(9, 32), 256>>>(
        h2hi, h2lo, nullptr, nullptr, kvbwhi, kvbwlo, kvb_b,
        kvbP, nullptr, nullptr, KVB_N, 512);

    // Oja update
    oja_kernel<<<B * H, 128>>>(kvbP, W, out);
}

// round 6
// speedup vs baseline: 1.6262x; 1.1095x over previous
#include <cuda_runtime.h>
#include <cuda_bf16.h>
#include <math.h>
#include <stdint.h>

#define B 4096
#define LATENT 512
#define H 8
#define D 64
#define KVB_N (H * (2 * D + 1))   // 1032

// ---------------- scratch (device globals; no allocation allowed) -----------
__device__ float g_h[B * LATENT];                 // post-GEMM1 / post-LN (fp32)
__device__ float g_h2[B * LATENT];                // post-GEMM2 (fp32)
__device__ float g_kvb[B * KVB_N];                // post-GEMM3 (fp32)
__device__ __nv_bfloat16 g_ipwT_hi[512 * 512],    g_ipwT_lo[512 * 512];     // [N=512,K=512]
__device__ __nv_bfloat16 g_mgwT_hi[512 * 1024],   g_mgwT_lo[512 * 1024];    // [N=512,K=1024]
__device__ __nv_bfloat16 g_kvbwT_hi[KVB_N * 512], g_kvbwT_lo[KVB_N * 512];  // [N=1032,K=512]

// ---------------- helpers ----------------------------------------------------
__device__ __forceinline__ uint32_t smem_u32(const void* p) {
    uint32_t a;
    asm("{ .reg .u64 t; cvta.to.shared.u64 t, %1; cvt.u32.u64 %0, t; }"
        : "=r"(a) : "l"(p));
    return a;
}
__device__ __forceinline__ void ldm_x4(uint32_t (&r)[4], uint32_t addr) {
    asm volatile("ldmatrix.sync.aligned.m8n8.x4.shared.b16 {%0,%1,%2,%3}, [%4];"
        : "=r"(r[0]), "=r"(r[1]), "=r"(r[2]), "=r"(r[3]) : "r"(addr));
}
__device__ __forceinline__ void mma16816(float* c, const uint32_t* a,
                                         uint32_t b0, uint32_t b1) {
    asm volatile("mma.sync.aligned.m16n8k16.row.col.f32.bf16.bf16.f32 "
        "{%0,%1,%2,%3}, {%4,%5,%6,%7}, {%8,%9}, {%0,%1,%2,%3};"
        : "+f"(c[0]), "+f"(c[1]), "+f"(c[2]), "+f"(c[3])
        : "r"(a[0]), "r"(a[1]), "r"(a[2]), "r"(a[3]), "r"(b0), "r"(b1));
}
__device__ __forceinline__ void split1(float v, __nv_bfloat16& h, __nv_bfloat16& l) {
    h = __float2bfloat16(v);
    l = __float2bfloat16(v - __bfloat162float(h));
}
__device__ __forceinline__ uint32_t packbf(__nv_bfloat16 a, __nv_bfloat16 b) {
    __nv_bfloat162 p; p.x = a; p.y = b;
    return *(uint32_t*)&p;
}
// split 8 fp32 -> packed hi/lo uint4 (8 bf16 each)
__device__ __forceinline__ void split8(const float4& a, const float4& b,
                                       uint4& hp, uint4& lp) {
    __nv_bfloat16 h0,l0,h1,l1,h2,l2,h3,l3,h4,l4,h5,l5,h6,l6,h7,l7;
    split1(a.x,h0,l0); split1(a.y,h1,l1); split1(a.z,h2,l2); split1(a.w,h3,l3);
    split1(b.x,h4,l4); split1(b.y,h5,l5); split1(b.z,h6,l6); split1(b.w,h7,l7);
    hp.x = packbf(h0,h1); hp.y = packbf(h2,h3); hp.z = packbf(h4,h5); hp.w = packbf(h6,h7);
    lp.x = packbf(l0,l1); lp.y = packbf(l2,l3); lp.z = packbf(l4,l5); lp.w = packbf(l6,l7);
}

// ---------------- weight transpose+split (tiled, coalesced) -----------------
// src [K,N] fp32 -> hi/lo [N,K] bf16
__global__ __launch_bounds__(256) void tsplit_tiled(
    const float* __restrict__ src, __nv_bfloat16* __restrict__ hi,
    __nv_bfloat16* __restrict__ lo, int K, int N)
{
    __shared__ __nv_bfloat16 th[32][36], tl[32][36];
    int k0 = blockIdx.x * 32, n0 = blockIdx.y * 32;
    int t = threadIdx.x;
    {
        int r  = t >> 3;            // k within tile
        int c4 = (t & 7) * 4;       // n within tile
        int gk = k0 + r;
        int gn = n0 + c4;
        float4 v = make_float4(0.f, 0.f, 0.f, 0.f);
        if (gn + 3 < N) {
            v = *(const float4*)(src + (size_t)gk * N + gn);
        } else {
            if (gn + 0 < N) v.x = src[(size_t)gk * N + gn + 0];
            if (gn + 1 < N) v.y = src[(size_t)gk * N + gn + 1];
            if (gn + 2 < N) v.z = src[(size_t)gk * N + gn + 2];
            if (gn + 3 < N) v.w = src[(size_t)gk * N + gn + 3];
        }
        __nv_bfloat16 h, l;
        split1(v.x, h, l); th[r][c4 + 0] = h; tl[r][c4 + 0] = l;
        split1(v.y, h, l); th[r][c4 + 1] = h; tl[r][c4 + 1] = l;
        split1(v.z, h, l); th[r][c4 + 2] = h; tl[r][c4 + 2] = l;
        split1(v.w, h, l); th[r][c4 + 3] = h; tl[r][c4 + 3] = l;
    }
    __syncthreads();
    {
        int n  = t >> 3;            // n within tile
        int k4 = (t & 7) * 4;       // k within tile
        int gn = n0 + n;
        if (gn < N) {
            uint2 ph, pl;
            ph.x = packbf(th[k4 + 0][n], th[k4 + 1][n]);
            ph.y = packbf(th[k4 + 2][n], th[k4 + 3][n]);
            pl.x = packbf(tl[k4 + 0][n], tl[k4 + 1][n]);
            pl.y = packbf(tl[k4 + 2][n], tl[k4 + 3][n]);
            *(uint2*)(hi + (size_t)gn * K + k0 + k4) = ph;
            *(uint2*)(lo + (size_t)gn * K + k0 + k4) = pl;
        }
    }
}

// ---------------- mma.sync GEMM (fp32 activations, split on stage) ----------
// C[M=4096,N] = A[M,K] @ Bw^T + bias.  A fp32 (row stride 512; two arrays when
// CONCAT), Bw pre-transposed+split [N,K] bf16.
// 128x128 block tile, BK=32, 8 warps (2 M x 4 N), 64x32 per warp.
// Split precision: acc += Ahi*Bhi + Ahi*Blo + Alo*Bhi.
#define PAD 40   // bf16 elems per smem row (80 B) -> conflict-free ldmatrix

template <bool CONCAT>
__global__ __launch_bounds__(256) void gemm_mma(
    const float* __restrict__ A0, const float* __restrict__ A1,
    const __nv_bfloat16* __restrict__ Bwhi, const __nv_bfloat16* __restrict__ Bwlo,
    const float* __restrict__ bias, float* __restrict__ Cf, int N, int K)
{
    __shared__ __nv_bfloat16 As_hi[128][PAD], As_lo[128][PAD];
    __shared__ __nv_bfloat16 Bs_hi[128][PAD], Bs_lo[128][PAD];

    int t = threadIdx.x;
    int wid = t >> 5, lane = t & 31;
    int wy = wid & 1, wx = wid >> 1;               // 2 x 4 warps
    int row0 = blockIdx.y * 128;
    int col0 = blockIdx.x * 128;

    int srow = t >> 2;            // 0..63, +64 on second pass
    int sc16 = t & 3;             // 8-element k-chunk

    float acc[4][4][4] = {};

    float4 pA[2][2];
    uint4  pBh[2], pBl[2];

    auto loadg = [&](int ch) {
        int k0 = ch * 32;
        const float* Aa; int ka;
        if (CONCAT && k0 >= 512) { Aa = A1; ka = k0 - 512; }
        else                     { Aa = A0; ka = k0; }
        #pragma unroll
        for (int i = 0; i < 2; i++) {
            int r = srow + i * 64;
            const float* ap = Aa + (size_t)(row0 + r) * 512 + ka + sc16 * 8;
            pA[i][0] = *(const float4*)ap;
            pA[i][1] = *(const float4*)(ap + 4);
            int gn = col0 + r;
            uint4 bh = make_uint4(0,0,0,0), bl = bh;
            if (gn < N) {
                bh = *(const uint4*)(Bwhi + (size_t)gn * K + k0 + sc16 * 8);
                bl = *(const uint4*)(Bwlo + (size_t)gn * K + k0 + sc16 * 8);
            }
            pBh[i] = bh; pBl[i] = bl;
        }
    };
    auto stage = [&]() {
        #pragma unroll
        for (int i = 0; i < 2; i++) {
            int r = srow + i * 64;
            uint4 hp, lp;
            split8(pA[i][0], pA[i][1], hp, lp);
            *(uint4*)&As_hi[r][sc16 * 8] = hp;
            *(uint4*)&As_lo[r][sc16 * 8] = lp;
            *(uint4*)&Bs_hi[r][sc16 * 8] = pBh[i];
            *(uint4*)&Bs_lo[r][sc16 * 8] = pBl[i];
        }
    };

    uint32_t sAh = smem_u32(As_hi), sAl = smem_u32(As_lo);
    uint32_t sBh = smem_u32(Bs_hi), sBl = smem_u32(Bs_lo);

    int a_row_off = (lane & 7) + ((lane & 8) ? 8 : 0);
    int a_ch_off  = (lane & 16) ? 1 : 0;
    int b_row_off = (lane & 7) + ((lane & 16) ? 8 : 0);
    int b_ch_off  = (lane & 8) ? 1 : 0;

    int nch = K / 32;
    loadg(0);

    for (int ch = 0; ch < nch; ch++) {
        stage();
        __syncthreads();
        if (ch + 1 < nch) loadg(ch + 1);

        #pragma unroll
        for (int ks = 0; ks < 2; ks++) {
            uint32_t ah[4][4], al[4][4], bh[2][4], bl[2][4];
            int ac = (ks * 2 + a_ch_off) * 8;
            int bc = (ks * 2 + b_ch_off) * 8;
            #pragma unroll
            for (int mt = 0; mt < 4; mt++) {
                int r = wy * 64 + mt * 16 + a_row_off;
                uint32_t off = (uint32_t)(r * PAD + ac) * 2;
                ldm_x4(ah[mt], sAh + off);
                ldm_x4(al[mt], sAl + off);
            }
            #pragma unroll
            for (int nt2 = 0; nt2 < 2; nt2++) {
                int r = wx * 32 + nt2 * 16 + b_row_off;
                uint32_t off = (uint32_t)(r * PAD + bc) * 2;
                ldm_x4(bh[nt2], sBh + off);
                ldm_x4(bl[nt2], sBl + off);
            }
            #pragma unroll
            for (int mt = 0; mt < 4; mt++)
                #pragma unroll
                for (int nt = 0; nt < 4; nt++) {
                    uint32_t bh0 = bh[nt >> 1][(nt & 1) * 2];
                    uint32_t bh1 = bh[nt >> 1][(nt & 1) * 2 + 1];
                    uint32_t bl0 = bl[nt >> 1][(nt & 1) * 2];
                    uint32_t bl1 = bl[nt >> 1][(nt & 1) * 2 + 1];
                    mma16816(acc[mt][nt], ah[mt], bh0, bh1);
                    mma16816(acc[mt][nt], ah[mt], bl0, bl1);
                    mma16816(acc[mt][nt], al[mt], bh0, bh1);
                }
        }
        __syncthreads();
    }

    // ---- epilogue ----
    int qr = lane >> 2;
    int qc = (lane & 3) * 2;
    #pragma unroll
    for (int mt = 0; mt < 4; mt++) {
        #pragma unroll
        for (int nt = 0; nt < 4; nt++) {
            int gm = row0 + wy * 64 + mt * 16 + qr;
            int gc = col0 + wx * 32 + nt * 8 + qc;
            float* c = acc[mt][nt];
            if (gc < N) {
                float b0 = bias[gc], b1 = bias[gc + 1];
                *(float2*)(Cf + (size_t)gm * N + gc)       = make_float2(c[0] + b0, c[1] + b1);
                *(float2*)(Cf + (size_t)(gm + 8) * N + gc) = make_float2(c[2] + b0, c[3] + b1);
            }
        }
    }
}

// ---------------- LayerNorm over last dim (512), in place -------------------
__global__ __launch_bounds__(128) void ln_kernel(
    float* __restrict__ h, const float* __restrict__ g, const float* __restrict__ b)
{
    int row = blockIdx.x;
    float4* hp = (float4*)(h + (size_t)row * LATENT);
    int t = threadIdx.x;
    float4 v = hp[t];
    float s  = v.x + v.y + v.z + v.w;
    float sq = v.x*v.x + v.y*v.y + v.z*v.z + v.w*v.w;
    #pragma unroll
    for (int o = 16; o; o >>= 1) {
        s  += __shfl_xor_sync(0xffffffffu, s, o);
        sq += __shfl_xor_sync(0xffffffffu, sq, o);
    }
    __shared__ float rs[4], rq[4];
    int lane = t & 31, wid = t >> 5;
    if (lane == 0) { rs[wid] = s; rq[wid] = sq; }
    __syncthreads();
    float S  = rs[0]+rs[1]+rs[2]+rs[3];
    float SQ = rq[0]+rq[1]+rq[2]+rq[3];
    float mu  = S * (1.0f / LATENT);
    float var = SQ * (1.0f / LATENT) - mu * mu;
    float r = rsqrtf(var + 1e-5f);
    float4 gv = ((const float4*)g)[t];
    float4 bv = ((const float4*)b)[t];
    v.x = (v.x - mu) * r * gv.x + bv.x;
    v.y = (v.y - mu) * r * gv.y + bv.y;
    v.z = (v.z - mu) * r * gv.z + bv.z;
    v.w = (v.w - mu) * r * gv.w + bv.w;
    hp[t] = v;
}

// ---------------- Oja update: one block per (b,h), cooperative softmax ------
__global__ __launch_bounds__(128) void oja_kernel(
    const float* __restrict__ kvb, const float* __restrict__ W, float* __restrict__ out)
{
    int bh = blockIdx.x;
    const float* w = W   + (size_t)bh * (D * D);
    float*       o = out + (size_t)bh * (D * D);
    const float* kv = kvb + (size_t)(bh >> 3) * KVB_N + (size_t)(bh & 7) * (2 * D + 1);

    __shared__ float Ws[D * D];
    __shared__ float vs[D], ksc[D];
    __shared__ float wmax[4], wsum[4];
    int t = threadIdx.x;
    int wid = t >> 5, lane = t & 31;

    #pragma unroll
    for (int i = t; i < (D * D) / 4; i += 128)
        ((float4*)Ws)[i] = ((const float4*)w)[i];
    if (t < D) vs[t] = tanhf(kv[D + t]);
    __syncthreads();

    float logit = -1e30f;
    if (t < D) {
        float acc = 0.f;
        #pragma unroll 16
        for (int d = 0; d < D; d++)
            acc = fmaf(Ws[d * D + t], vs[d], acc);
        logit = kv[t] - acc;
    }
    // max over t<64 (warps 0,1)
    float m = logit;
    #pragma unroll
    for (int s2 = 16; s2; s2 >>= 1) m = fmaxf(m, __shfl_xor_sync(0xffffffffu, m, s2));
    if (lane == 0) wmax[wid] = m;
    __syncthreads();
    float mm = fmaxf(wmax[0], wmax[1]);

    float e = 0.f, s = 0.f;
    if (t < D) { e = expf(logit - mm); s = e; }
    #pragma unroll
    for (int s2 = 16; s2; s2 >>= 1) s += __shfl_xor_sync(0xffffffffu, s, s2);
    if (lane == 0) wsum[wid] = s;
    __syncthreads();
    float ss = wsum[0] + wsum[1];

    if (t < D) {
        float lr = 1.0f / (1.0f + expf(-kv[2 * D]));
        ksc[t] = e * (lr / ss);
    }
    __syncthreads();

    #pragma unroll
    for (int i = t; i < (D * D) / 4; i += 128) {
        float4 wv = ((const float4*)Ws)[i];
        int d  = i >> 4;
        int e0 = (i * 4) & (D - 1);
        float vd = vs[d];
        float4 r;
        r.x = fmaf(vd, ksc[e0 + 0], wv.x);
        r.y = fmaf(vd, ksc[e0 + 1], wv.y);
        r.z = fmaf(vd, ksc[e0 + 2], wv.z);
        r.w = fmaf(vd, ksc[e0 + 3], wv.w);
        ((float4*)o)[i] = r;
    }
}

// ---------------- launch -----------------------------------------------------
extern "C" void kernel_launch(void* const* d_in, const int* in_sizes, int n_in,
                              void* d_out, int out_size)
{
    const float* x     = (const float*)d_in[0];
    const float* z     = (const float*)d_in[1];
    const float* W     = (const float*)d_in[2];
    const float* ip_w  = (const float*)d_in[3];
    const float* ip_b  = (const float*)d_in[4];
    const float* ln_g  = (const float*)d_in[5];
    const float* ln_b  = (const float*)d_in[6];
    const float* mg_w  = (const float*)d_in[7];
    const float* mg_b  = (const float*)d_in[8];
    const float* kvb_w = (const float*)d_in[9];
    const float* kvb_b = (const float*)d_in[10];
    float* out = (float*)d_out;

    float *hP, *h2P, *kvbP;
    __nv_bfloat16 *ipwhi,*ipwlo,*mgwhi,*mgwlo,*kvbwhi,*kvbwlo;
    cudaGetSymbolAddress((void**)&hP,    g_h);
    cudaGetSymbolAddress((void**)&h2P,   g_h2);
    cudaGetSymbolAddress((void**)&kvbP,  g_kvb);
    cudaGetSymbolAddress((void**)&ipwhi, g_ipwT_hi);  cudaGetSymbolAddress((void**)&ipwlo, g_ipwT_lo);
    cudaGetSymbolAddress((void**)&mgwhi, g_mgwT_hi);  cudaGetSymbolAddress((void**)&mgwlo, g_mgwT_lo);
    cudaGetSymbolAddress((void**)&kvbwhi,g_kvbwT_hi); cudaGetSymbolAddress((void**)&kvbwlo,g_kvbwT_lo);

    // weight transpose + split (coalesced, tiled)
    tsplit_tiled<<<dim3(512/32, 512/32),  256>>>(ip_w,  ipwhi,  ipwlo,  512, 512);
    tsplit_tiled<<<dim3(1024/32, 512/32), 256>>>(mg_w,  mgwhi,  mgwlo,  1024, 512);
    tsplit_tiled<<<dim3(512/32, (KVB_N+31)/32), 256>>>(kvb_w, kvbwhi, kvbwlo, 512, KVB_N);

    // GEMM1: h = x @ ip_w + ip_b   (N=512, K=512)
    gemm_mma<false><<<dim3(4, 32), 256>>>(x, nullptr, ipwhi, ipwlo, ip_b, hP, 512, 512);

    // LayerNorm in place
    ln_kernel<<<B, 128>>>(hP, ln_g, ln_b);

    // GEMM2: h2 = [h, z] @ mg_w + mg_b  (N=512, K=1024)
    gemm_mma<true><<<dim3(4, 32), 256>>>(hP, z, mgwhi, mgwlo, mg_b, h2P, 512, 1024);

    // GEMM3: kvb = h2 @ kvb_w + kvb_b  (N=1032, K=512)
    gemm_mma<false><<<dim3(9, 32), 256>>>(h2P, nullptr, kvbwhi, kvbwlo, kvb_b, kvbP, KVB_N, 512);

    // Oja update
    oja_kernel<<<B * H, 128>>>(kvbP, W, out);
}

// round 7
// speedup vs baseline: 1.6306x; 1.0027x over previous
#include <cuda_runtime.h>
#include <cuda_bf16.h>
#include <math.h>
#include <stdint.h>

#define B 4096
#define LATENT 512
#define H 8
#define D 64
#define KVB_N (H * (2 * D + 1))   // 1032

// ---------------- scratch (device globals; no allocation allowed) -----------
__device__ float g_h[B * LATENT];                 // post-GEMM1 / post-LN (fp32)
__device__ float g_h2[B * LATENT];                // post-GEMM2 (fp32)
__device__ float g_kvb[B * KVB_N];                // post-GEMM3 (fp32)
__device__ __nv_bfloat16 g_ipwT_hi[512 * 512],    g_ipwT_lo[512 * 512];     // [N=512,K=512]
__device__ __nv_bfloat16 g_mgwT_hi[512 * 1024],   g_mgwT_lo[512 * 1024];    // [N=512,K=1024]
__device__ __nv_bfloat16 g_kvbwT_hi[KVB_N * 512], g_kvbwT_lo[KVB_N * 512];  // [N=1032,K=512]

// ---------------- helpers ----------------------------------------------------
__device__ __forceinline__ uint32_t smem_u32(const void* p) {
    uint32_t a;
    asm("{ .reg .u64 t; cvta.to.shared.u64 t, %1; cvt.u32.u64 %0, t; }"
        : "=r"(a) : "l"(p));
    return a;
}
__device__ __forceinline__ void ldm_x4(uint32_t (&r)[4], uint32_t addr) {
    asm volatile("ldmatrix.sync.aligned.m8n8.x4.shared.b16 {%0,%1,%2,%3}, [%4];"
        : "=r"(r[0]), "=r"(r[1]), "=r"(r[2]), "=r"(r[3]) : "r"(addr));
}
__device__ __forceinline__ void mma16816(float* c, const uint32_t* a,
                                         uint32_t b0, uint32_t b1) {
    asm volatile("mma.sync.aligned.m16n8k16.row.col.f32.bf16.bf16.f32 "
        "{%0,%1,%2,%3}, {%4,%5,%6,%7}, {%8,%9}, {%0,%1,%2,%3};"
        : "+f"(c[0]), "+f"(c[1]), "+f"(c[2]), "+f"(c[3])
        : "r"(a[0]), "r"(a[1]), "r"(a[2]), "r"(a[3]), "r"(b0), "r"(b1));
}
__device__ __forceinline__ void split1(float v, __nv_bfloat16& h, __nv_bfloat16& l) {
    h = __float2bfloat16(v);
    l = __float2bfloat16(v - __bfloat162float(h));
}
__device__ __forceinline__ uint32_t packbf(__nv_bfloat16 a, __nv_bfloat16 b) {
    __nv_bfloat162 p; p.x = a; p.y = b;
    return *(uint32_t*)&p;
}
// split 8 fp32 -> packed hi/lo uint4 (8 bf16 each)
__device__ __forceinline__ void split8(const float4& a, const float4& b,
                                       uint4& hp, uint4& lp) {
    __nv_bfloat16 h0,l0,h1,l1,h2,l2,h3,l3,h4,l4,h5,l5,h6,l6,h7,l7;
    split1(a.x,h0,l0); split1(a.y,h1,l1); split1(a.z,h2,l2); split1(a.w,h3,l3);
    split1(b.x,h4,l4); split1(b.y,h5,l5); split1(b.z,h6,l6); split1(b.w,h7,l7);
    hp.x = packbf(h0,h1); hp.y = packbf(h2,h3); hp.z = packbf(h4,h5); hp.w = packbf(h6,h7);
    lp.x = packbf(l0,l1); lp.y = packbf(l2,l3); lp.z = packbf(l4,l5); lp.w = packbf(l6,l7);
}

// ---------------- weight transpose+split (tiled, coalesced) -----------------
// src [K,N] fp32 -> hi/lo [N,K] bf16
__global__ __launch_bounds__(256) void tsplit_tiled(
    const float* __restrict__ src, __nv_bfloat16* __restrict__ hi,
    __nv_bfloat16* __restrict__ lo, int K, int N)
{
    __shared__ __nv_bfloat16 th[32][36], tl[32][36];
    int k0 = blockIdx.x * 32, n0 = blockIdx.y * 32;
    int t = threadIdx.x;
    {
        int r  = t >> 3;
        int c4 = (t & 7) * 4;
        int gk = k0 + r;
        int gn = n0 + c4;
        float4 v = make_float4(0.f, 0.f, 0.f, 0.f);
        if (gn + 3 < N) {
            v = *(const float4*)(src + (size_t)gk * N + gn);
        } else {
            if (gn + 0 < N) v.x = src[(size_t)gk * N + gn + 0];
            if (gn + 1 < N) v.y = src[(size_t)gk * N + gn + 1];
            if (gn + 2 < N) v.z = src[(size_t)gk * N + gn + 2];
            if (gn + 3 < N) v.w = src[(size_t)gk * N + gn + 3];
        }
        __nv_bfloat16 h, l;
        split1(v.x, h, l); th[r][c4 + 0] = h; tl[r][c4 + 0] = l;
        split1(v.y, h, l); th[r][c4 + 1] = h; tl[r][c4 + 1] = l;
        split1(v.z, h, l); th[r][c4 + 2] = h; tl[r][c4 + 2] = l;
        split1(v.w, h, l); th[r][c4 + 3] = h; tl[r][c4 + 3] = l;
    }
    __syncthreads();
    {
        int n  = t >> 3;
        int k4 = (t & 7) * 4;
        int gn = n0 + n;
        if (gn < N) {
            uint2 ph, pl;
            ph.x = packbf(th[k4 + 0][n], th[k4 + 1][n]);
            ph.y = packbf(th[k4 + 2][n], th[k4 + 3][n]);
            pl.x = packbf(tl[k4 + 0][n], tl[k4 + 1][n]);
            pl.y = packbf(tl[k4 + 2][n], tl[k4 + 3][n]);
            *(uint2*)(hi + (size_t)gn * K + k0 + k4) = ph;
            *(uint2*)(lo + (size_t)gn * K + k0 + k4) = pl;
        }
    }
}

// ---------------- mma.sync GEMM (fp32 activations, split on stage) ----------
// C[M=4096,N] = A[M,K] @ Bw^T + bias.  A fp32 (row stride 512; two arrays when
// CONCAT), Bw pre-transposed+split [N,K] bf16.
// 128x64 block tile, BK=32, 8 warps (4 M x 2 N), warp tile 32x32, 2 blocks/SM.
// Split precision: acc += Ahi*Bhi + Ahi*Blo + Alo*Bhi.
#define PAD 40   // bf16 elems per smem row (80 B) -> conflict-free ldmatrix

template <bool CONCAT>
__global__ __launch_bounds__(256, 2) void gemm_mma(
    const float* __restrict__ A0, const float* __restrict__ A1,
    const __nv_bfloat16* __restrict__ Bwhi, const __nv_bfloat16* __restrict__ Bwlo,
    const float* __restrict__ bias, float* __restrict__ Cf, int N, int K)
{
    __shared__ __nv_bfloat16 As_hi[128][PAD], As_lo[128][PAD];
    __shared__ __nv_bfloat16 Bs_hi[64][PAD],  Bs_lo[64][PAD];

    int t = threadIdx.x;
    int wid = t >> 5, lane = t & 31;
    int wy = wid & 3, wx = wid >> 2;               // 4 M x 2 N warps
    int row0 = blockIdx.y * 128;
    int col0 = blockIdx.x * 64;

    int srow = t >> 2;            // 0..63 (A: +64 second pass; B: direct)
    int sc16 = t & 3;             // 8-element k-chunk

    float acc[2][4][4] = {};

    float4 pA[2][2];
    uint4  pBh, pBl;

    auto loadg = [&](int ch) {
        int k0 = ch * 32;
        const float* Aa; int ka;
        if (CONCAT && k0 >= 512) { Aa = A1; ka = k0 - 512; }
        else                     { Aa = A0; ka = k0; }
        #pragma unroll
        for (int i = 0; i < 2; i++) {
            int r = srow + i * 64;
            const float* ap = Aa + (size_t)(row0 + r) * 512 + ka + sc16 * 8;
            pA[i][0] = *(const float4*)ap;
            pA[i][1] = *(const float4*)(ap + 4);
        }
        int gn = col0 + srow;
        uint4 bh = make_uint4(0,0,0,0), bl = bh;
        if (gn < N) {
            bh = *(const uint4*)(Bwhi + (size_t)gn * K + k0 + sc16 * 8);
            bl = *(const uint4*)(Bwlo + (size_t)gn * K + k0 + sc16 * 8);
        }
        pBh = bh; pBl = bl;
    };
    auto stage = [&]() {
        #pragma unroll
        for (int i = 0; i < 2; i++) {
            int r = srow + i * 64;
            uint4 hp, lp;
            split8(pA[i][0], pA[i][1], hp, lp);
            *(uint4*)&As_hi[r][sc16 * 8] = hp;
            *(uint4*)&As_lo[r][sc16 * 8] = lp;
        }
        *(uint4*)&Bs_hi[srow][sc16 * 8] = pBh;
        *(uint4*)&Bs_lo[srow][sc16 * 8] = pBl;
    };

    uint32_t sAh = smem_u32(As_hi), sAl = smem_u32(As_lo);
    uint32_t sBh = smem_u32(Bs_hi), sBl = smem_u32(Bs_lo);

    int a_row_off = (lane & 7) + ((lane & 8) ? 8 : 0);
    int a_ch_off  = (lane & 16) ? 1 : 0;
    int b_row_off = (lane & 7) + ((lane & 16) ? 8 : 0);
    int b_ch_off  = (lane & 8) ? 1 : 0;

    int nch = K / 32;
    loadg(0);

    for (int ch = 0; ch < nch; ch++) {
        stage();
        __syncthreads();
        if (ch + 1 < nch) loadg(ch + 1);

        #pragma unroll
        for (int ks = 0; ks < 2; ks++) {
            uint32_t ah[2][4], al[2][4], bh[2][4], bl[2][4];
            int ac = (ks * 2 + a_ch_off) * 8;
            int bc = (ks * 2 + b_ch_off) * 8;
            #pragma unroll
            for (int mt = 0; mt < 2; mt++) {
                int r = wy * 32 + mt * 16 + a_row_off;
                uint32_t off = (uint32_t)(r * PAD + ac) * 2;
                ldm_x4(ah[mt], sAh + off);
                ldm_x4(al[mt], sAl + off);
            }
            #pragma unroll
            for (int nt2 = 0; nt2 < 2; nt2++) {
                int r = wx * 32 + nt2 * 16 + b_row_off;
                uint32_t off = (uint32_t)(r * PAD + bc) * 2;
                ldm_x4(bh[nt2], sBh + off);
                ldm_x4(bl[nt2], sBl + off);
            }
            #pragma unroll
            for (int mt = 0; mt < 2; mt++)
                #pragma unroll
                for (int nt = 0; nt < 4; nt++) {
                    uint32_t bh0 = bh[nt >> 1][(nt & 1) * 2];
                    uint32_t bh1 = bh[nt >> 1][(nt & 1) * 2 + 1];
                    uint32_t bl0 = bl[nt >> 1][(nt & 1) * 2];
                    uint32_t bl1 = bl[nt >> 1][(nt & 1) * 2 + 1];
                    mma16816(acc[mt][nt], ah[mt], bh0, bh1);
                    mma16816(acc[mt][nt], ah[mt], bl0, bl1);
                    mma16816(acc[mt][nt], al[mt], bh0, bh1);
                }
        }
        __syncthreads();
    }

    // ---- epilogue ----
    int qr = lane >> 2;
    int qc = (lane & 3) * 2;
    #pragma unroll
    for (int mt = 0; mt < 2; mt++) {
        #pragma unroll
        for (int nt = 0; nt < 4; nt++) {
            int gm = row0 + wy * 32 + mt * 16 + qr;
            int gc = col0 + wx * 32 + nt * 8 + qc;
            float* c = acc[mt][nt];
            if (gc < N) {
                float b0 = bias[gc], b1 = bias[gc + 1];
                *(float2*)(Cf + (size_t)gm * N + gc)       = make_float2(c[0] + b0, c[1] + b1);
                *(float2*)(Cf + (size_t)(gm + 8) * N + gc) = make_float2(c[2] + b0, c[3] + b1);
            }
        }
    }
}

// ---------------- LayerNorm over last dim (512), in place -------------------
__global__ __launch_bounds__(128) void ln_kernel(
    float* __restrict__ h, const float* __restrict__ g, const float* __restrict__ b)
{
    int row = blockIdx.x;
    float4* hp = (float4*)(h + (size_t)row * LATENT);
    int t = threadIdx.x;
    float4 v = hp[t];
    float s  = v.x + v.y + v.z + v.w;
    float sq = v.x*v.x + v.y*v.y + v.z*v.z + v.w*v.w;
    #pragma unroll
    for (int o = 16; o; o >>= 1) {
        s  += __shfl_xor_sync(0xffffffffu, s, o);
        sq += __shfl_xor_sync(0xffffffffu, sq, o);
    }
    __shared__ float rs[4], rq[4];
    int lane = t & 31, wid = t >> 5;
    if (lane == 0) { rs[wid] = s; rq[wid] = sq; }
    __syncthreads();
    float S  = rs[0]+rs[1]+rs[2]+rs[3];
    float SQ = rq[0]+rq[1]+rq[2]+rq[3];
    float mu  = S * (1.0f / LATENT);
    float var = SQ * (1.0f / LATENT) - mu * mu;
    float r = rsqrtf(var + 1e-5f);
    float4 gv = ((const float4*)g)[t];
    float4 bv = ((const float4*)b)[t];
    v.x = (v.x - mu) * r * gv.x + bv.x;
    v.y = (v.y - mu) * r * gv.y + bv.y;
    v.z = (v.z - mu) * r * gv.z + bv.z;
    v.w = (v.w - mu) * r * gv.w + bv.w;
    hp[t] = v;
}

// ---------------- Oja update: one block per (b,h), cooperative softmax ------
__global__ __launch_bounds__(128) void oja_kernel(
    const float* __restrict__ kvb, const float* __restrict__ W, float* __restrict__ out)
{
    int bh = blockIdx.x;
    const float* w = W   + (size_t)bh * (D * D);
    float*       o = out + (size_t)bh * (D * D);
    const float* kv = kvb + (size_t)(bh >> 3) * KVB_N + (size_t)(bh & 7) * (2 * D + 1);

    __shared__ float Ws[D * D];
    __shared__ float vs[D], ksc[D];
    __shared__ float wmax[4], wsum[4];
    int t = threadIdx.x;
    int wid = t >> 5, lane = t & 31;

    #pragma unroll
    for (int i = t; i < (D * D) / 4; i += 128)
        ((float4*)Ws)[i] = ((const float4*)w)[i];
    if (t < D) vs[t] = tanhf(kv[D + t]);
    __syncthreads();

    float logit = -1e30f;
    if (t < D) {
        float acc = 0.f;
        #pragma unroll 16
        for (int d = 0; d < D; d++)
            acc = fmaf(Ws[d * D + t], vs[d], acc);
        logit = kv[t] - acc;
    }
    float m = logit;
    #pragma unroll
    for (int s2 = 16; s2; s2 >>= 1) m = fmaxf(m, __shfl_xor_sync(0xffffffffu, m, s2));
    if (lane == 0) wmax[wid] = m;
    __syncthreads();
    float mm = fmaxf(wmax[0], wmax[1]);

    float e = 0.f, s = 0.f;
    if (t < D) { e = expf(logit - mm); s = e; }
    #pragma unroll
    for (int s2 = 16; s2; s2 >>= 1) s += __shfl_xor_sync(0xffffffffu, s, s2);
    if (lane == 0) wsum[wid] = s;
    __syncthreads();
    float ss = wsum[0] + wsum[1];

    if (t < D) {
        float lr = 1.0f / (1.0f + expf(-kv[2 * D]));
        ksc[t] = e * (lr / ss);
    }
    __syncthreads();

    #pragma unroll
    for (int i = t; i < (D * D) / 4; i += 128) {
        float4 wv = ((const float4*)Ws)[i];
        int d  = i >> 4;
        int e0 = (i * 4) & (D - 1);
        float vd = vs[d];
        float4 r;
        r.x = fmaf(vd, ksc[e0 + 0], wv.x);
        r.y = fmaf(vd, ksc[e0 + 1], wv.y);
        r.z = fmaf(vd, ksc[e0 + 2], wv.z);
        r.w = fmaf(vd, ksc[e0 + 3], wv.w);
        ((float4*)o)[i] = r;
    }
}

// ---------------- launch -----------------------------------------------------
extern "C" void kernel_launch(void* const* d_in, const int* in_sizes, int n_in,
                              void* d_out, int out_size)
{
    const float* x     = (const float*)d_in[0];
    const float* z     = (const float*)d_in[1];
    const float* W     = (const float*)d_in[2];
    const float* ip_w  = (const float*)d_in[3];
    const float* ip_b  = (const float*)d_in[4];
    const float* ln_g  = (const float*)d_in[5];
    const float* ln_b  = (const float*)d_in[6];
    const float* mg_w  = (const float*)d_in[7];
    const float* mg_b  = (const float*)d_in[8];
    const float* kvb_w = (const float*)d_in[9];
    const float* kvb_b = (const float*)d_in[10];
    float* out = (float*)d_out;

    float *hP, *h2P, *kvbP;
    __nv_bfloat16 *ipwhi,*ipwlo,*mgwhi,*mgwlo,*kvbwhi,*kvbwlo;
    cudaGetSymbolAddress((void**)&hP,    g_h);
    cudaGetSymbolAddress((void**)&h2P,   g_h2);
    cudaGetSymbolAddress((void**)&kvbP,  g_kvb);
    cudaGetSymbolAddress((void**)&ipwhi, g_ipwT_hi);  cudaGetSymbolAddress((void**)&ipwlo, g_ipwT_lo);
    cudaGetSymbolAddress((void**)&mgwhi, g_mgwT_hi);  cudaGetSymbolAddress((void**)&mgwlo, g_mgwT_lo);
    cudaGetSymbolAddress((void**)&kvbwhi,g_kvbwT_hi); cudaGetSymbolAddress((void**)&kvbwlo,g_kvbwT_lo);

    // weight transpose + split (coalesced, tiled)
    tsplit_tiled<<<dim3(512/32, 512/32),  256>>>(ip_w,  ipwhi,  ipwlo,  512, 512);
    tsplit_tiled<<<dim3(1024/32, 512/32), 256>>>(mg_w,  mgwhi,  mgwlo,  1024, 512);
    tsplit_tiled<<<dim3(512/32, (KVB_N+31)/32), 256>>>(kvb_w, kvbwhi, kvbwlo, 512, KVB_N);

    // GEMM1: h = x @ ip_w + ip_b   (N=512, K=512)
    gemm_mma<false><<<dim3(8, 32), 256>>>(x, nullptr, ipwhi, ipwlo, ip_b, hP, 512, 512);

    // LayerNorm in place
    ln_kernel<<<B, 128>>>(hP, ln_g, ln_b);

    // GEMM2: h2 = [h, z] @ mg_w + mg_b  (N=512, K=1024)
    gemm_mma<true><<<dim3(8, 32), 256>>>(hP, z, mgwhi, mgwlo, mg_b, h2P, 512, 1024);

    // GEMM3: kvb = h2 @ kvb_w + kvb_b  (N=1032, K=512)
    gemm_mma<false><<<dim3((KVB_N + 63) / 64, 32), 256>>>(
        h2P, nullptr, kvbwhi, kvbwlo, kvb_b, kvbP, KVB_N, 512);

    // Oja update
    oja_kernel<<<B * H, 128>>>(kvbP, W, out);
}

// round 8
// speedup vs baseline: 1.6314x; 1.0005x over previous
#include <cuda_runtime.h>
#include <cuda_bf16.h>
#include <math.h>
#include <stdint.h>

#define B 4096
#define LATENT 512
#define H 8
#define D 64
#define KVB_N (H * (2 * D + 1))   // 1032

// ---------------- scratch (device globals; no allocation allowed) -----------
__device__ float g_h[B * LATENT];                 // post-GEMM1 / post-LN (fp32)
__device__ float g_h2[B * LATENT];                // post-GEMM2 (fp32)
__device__ float g_kvb[B * KVB_N];                // post-GEMM3 (fp32)
__device__ __nv_bfloat16 g_ipwT_hi[512 * 512],    g_ipwT_lo[512 * 512];     // [N=512,K=512]
__device__ __nv_bfloat16 g_mgwT_hi[512 * 1024],   g_mgwT_lo[512 * 1024];    // [N=512,K=1024]
__device__ __nv_bfloat16 g_kvbwT_hi[KVB_N * 512], g_kvbwT_lo[KVB_N * 512];  // [N=1032,K=512]

// ---------------- helpers ----------------------------------------------------
__device__ __forceinline__ uint32_t smem_u32(const void* p) {
    uint32_t a;
    asm("{ .reg .u64 t; cvta.to.shared.u64 t, %1; cvt.u32.u64 %0, t; }"
        : "=r"(a) : "l"(p));
    return a;
}
__device__ __forceinline__ void ldm_x4(uint32_t (&r)[4], uint32_t addr) {
    asm volatile("ldmatrix.sync.aligned.m8n8.x4.shared.b16 {%0,%1,%2,%3}, [%4];"
        : "=r"(r[0]), "=r"(r[1]), "=r"(r[2]), "=r"(r[3]) : "r"(addr));
}
__device__ __forceinline__ void mma16816(float* c, const uint32_t* a,
                                         uint32_t b0, uint32_t b1) {
    asm volatile("mma.sync.aligned.m16n8k16.row.col.f32.bf16.bf16.f32 "
        "{%0,%1,%2,%3}, {%4,%5,%6,%7}, {%8,%9}, {%0,%1,%2,%3};"
        : "+f"(c[0]), "+f"(c[1]), "+f"(c[2]), "+f"(c[3])
        : "r"(a[0]), "r"(a[1]), "r"(a[2]), "r"(a[3]), "r"(b0), "r"(b1));
}
__device__ __forceinline__ void cpasync16(uint32_t dst, const void* src) {
    asm volatile("cp.async.ca.shared.global [%0], [%1], 16;"
                 :: "r"(dst), "l"(src) : "memory");
}
__device__ __forceinline__ void split1(float v, __nv_bfloat16& h, __nv_bfloat16& l) {
    h = __float2bfloat16(v);
    l = __float2bfloat16(v - __bfloat162float(h));
}
__device__ __forceinline__ uint32_t packbf(__nv_bfloat16 a, __nv_bfloat16 b) {
    __nv_bfloat162 p; p.x = a; p.y = b;
    return *(uint32_t*)&p;
}
__device__ __forceinline__ void split8(const float4& a, const float4& b,
                                       uint4& hp, uint4& lp) {
    __nv_bfloat16 h0,l0,h1,l1,h2,l2,h3,l3,h4,l4,h5,l5,h6,l6,h7,l7;
    split1(a.x,h0,l0); split1(a.y,h1,l1); split1(a.z,h2,l2); split1(a.w,h3,l3);
    split1(b.x,h4,l4); split1(b.y,h5,l5); split1(b.z,h6,l6); split1(b.w,h7,l7);
    hp.x = packbf(h0,h1); hp.y = packbf(h2,h3); hp.z = packbf(h4,h5); hp.w = packbf(h6,h7);
    lp.x = packbf(l0,l1); lp.y = packbf(l2,l3); lp.z = packbf(l4,l5); lp.w = packbf(l6,l7);
}

// ---------------- weight transpose+split (tiled, coalesced) -----------------
__global__ __launch_bounds__(256) void tsplit_tiled(
    const float* __restrict__ src, __nv_bfloat16* __restrict__ hi,
    __nv_bfloat16* __restrict__ lo, int K, int N)
{
    __shared__ __nv_bfloat16 th[32][36], tl[32][36];
    int k0 = blockIdx.x * 32, n0 = blockIdx.y * 32;
    int t = threadIdx.x;
    {
        int r  = t >> 3;
        int c4 = (t & 7) * 4;
        int gk = k0 + r;
        int gn = n0 + c4;
        float4 v = make_float4(0.f, 0.f, 0.f, 0.f);
        if (gn + 3 < N) {
            v = *(const float4*)(src + (size_t)gk * N + gn);
        } else {
            if (gn + 0 < N) v.x = src[(size_t)gk * N + gn + 0];
            if (gn + 1 < N) v.y = src[(size_t)gk * N + gn + 1];
            if (gn + 2 < N) v.z = src[(size_t)gk * N + gn + 2];
            if (gn + 3 < N) v.w = src[(size_t)gk * N + gn + 3];
        }
        __nv_bfloat16 h, l;
        split1(v.x, h, l); th[r][c4 + 0] = h; tl[r][c4 + 0] = l;
        split1(v.y, h, l); th[r][c4 + 1] = h; tl[r][c4 + 1] = l;
        split1(v.z, h, l); th[r][c4 + 2] = h; tl[r][c4 + 2] = l;
        split1(v.w, h, l); th[r][c4 + 3] = h; tl[r][c4 + 3] = l;
    }
    __syncthreads();
    {
        int n  = t >> 3;
        int k4 = (t & 7) * 4;
        int gn = n0 + n;
        if (gn < N) {
            uint2 ph, pl;
            ph.x = packbf(th[k4 + 0][n], th[k4 + 1][n]);
            ph.y = packbf(th[k4 + 2][n], th[k4 + 3][n]);
            pl.x = packbf(tl[k4 + 0][n], tl[k4 + 1][n]);
            pl.y = packbf(tl[k4 + 2][n], tl[k4 + 3][n]);
            *(uint2*)(hi + (size_t)gn * K + k0 + k4) = ph;
            *(uint2*)(lo + (size_t)gn * K + k0 + k4) = pl;
        }
    }
}

// ---------------- pipelined mma.sync GEMM ------------------------------------
// C[M=4096,N] = A[M,K] @ Bw^T + bias; A fp32 (split on stage), Bw bf16 hi/lo.
// 128x64 block tile, BK=32, 8 warps (4Mx2N), warp tile 32x32.
// Double-buffered dynamic smem; B tiles via cp.async; 1 sync per chunk.
#define PAD 40
#define A_BUF_B (128 * PAD * 2)         // 10240 bytes per A array per buffer
#define B_BUF_B (64 * PAD * 2)          // 5120 bytes per B array per buffer
#define OFF_AH  0
#define OFF_AL  (2 * A_BUF_B)           // 20480
#define OFF_BH  (4 * A_BUF_B)           // 40960
#define OFF_BL  (4 * A_BUF_B + 2 * B_BUF_B)   // 51200
#define SMEM_TOT (4 * A_BUF_B + 4 * B_BUF_B)  // 61440

template <bool CONCAT>
__global__ __launch_bounds__(256, 2) void gemm_mma(
    const float* __restrict__ A0, const float* __restrict__ A1,
    const __nv_bfloat16* __restrict__ Bwhi, const __nv_bfloat16* __restrict__ Bwlo,
    const float* __restrict__ bias, float* __restrict__ Cf, int N, int K)
{
    extern __shared__ char smem[];
    uint32_t sb = smem_u32(smem);

    int t = threadIdx.x;
    int wid = t >> 5, lane = t & 31;
    int wy = wid & 3, wx = wid >> 2;               // 4 M x 2 N warps
    int row0 = blockIdx.y * 128;
    int col0 = blockIdx.x * 64;

    int srow = t >> 2;            // 0..63
    int sc16 = t & 3;             // 16B k-chunk

    float acc[2][4][4] = {};
    float4 pA[2][2];

    const int gnB = col0 + srow;
    const bool bok = (gnB < N);

    auto loadgA = [&](int ch) {
        int k0 = ch * 32;
        const float* Aa; int ka;
        if (CONCAT && k0 >= 512) { Aa = A1; ka = k0 - 512; }
        else                     { Aa = A0; ka = k0; }
        #pragma unroll
        for (int i = 0; i < 2; i++) {
            int r = srow + i * 64;
            const float* ap = Aa + (size_t)(row0 + r) * 512 + ka + sc16 * 8;
            pA[i][0] = *(const float4*)ap;
            pA[i][1] = *(const float4*)(ap + 4);
        }
    };
    auto cpasyncB = [&](int ch, int buf) {
        if (!bok) return;
        int k0 = ch * 32;
        uint32_t d = sb + buf * B_BUF_B + (uint32_t)(srow * PAD + sc16 * 8) * 2;
        cpasync16(d + OFF_BH, Bwhi + (size_t)gnB * K + k0 + sc16 * 8);
        cpasync16(d + OFF_BL, Bwlo + (size_t)gnB * K + k0 + sc16 * 8);
    };
    auto stageA = [&](int buf) {
        #pragma unroll
        for (int i = 0; i < 2; i++) {
            int r = srow + i * 64;
            uint4 hp, lp;
            split8(pA[i][0], pA[i][1], hp, lp);
            uint32_t d = sb + buf * A_BUF_B + (uint32_t)(r * PAD + sc16 * 8) * 2;
            *(uint4*)(smem + (d - sb) + OFF_AH) = hp;
            *(uint4*)(smem + (d - sb) + OFF_AL) = lp;
        }
    };

    int a_row_off = (lane & 7) + ((lane & 8) ? 8 : 0);
    int a_ch_off  = (lane & 16) ? 1 : 0;
    int b_row_off = (lane & 7) + ((lane & 16) ? 8 : 0);
    int b_ch_off  = (lane & 8) ? 1 : 0;

    int nch = K / 32;

    // prologue: fill buffer 0
    loadgA(0);
    cpasyncB(0, 0);
    asm volatile("cp.async.commit_group;" ::: "memory");
    stageA(0);
    asm volatile("cp.async.wait_group 0;" ::: "memory");
    __syncthreads();

    int buf = 0;
    for (int ch = 0; ch < nch; ch++) {
        int nxt = ch + 1;
        if (nxt < nch) {
            loadgA(nxt);
            cpasyncB(nxt, buf ^ 1);
            asm volatile("cp.async.commit_group;" ::: "memory");
        }

        // compute on current buffer
        uint32_t aH = sb + OFF_AH + buf * A_BUF_B;
        uint32_t aL = sb + OFF_AL + buf * A_BUF_B;
        uint32_t bH = sb + OFF_BH + buf * B_BUF_B;
        uint32_t bL = sb + OFF_BL + buf * B_BUF_B;
        #pragma unroll
        for (int ks = 0; ks < 2; ks++) {
            uint32_t ah[2][4], al[2][4], bh[2][4], bl[2][4];
            int ac = (ks * 2 + a_ch_off) * 8;
            int bc = (ks * 2 + b_ch_off) * 8;
            #pragma unroll
            for (int mt = 0; mt < 2; mt++) {
                int r = wy * 32 + mt * 16 + a_row_off;
                uint32_t off = (uint32_t)(r * PAD + ac) * 2;
                ldm_x4(ah[mt], aH + off);
                ldm_x4(al[mt], aL + off);
            }
            #pragma unroll
            for (int nt2 = 0; nt2 < 2; nt2++) {
                int r = wx * 32 + nt2 * 16 + b_row_off;
                uint32_t off = (uint32_t)(r * PAD + bc) * 2;
                ldm_x4(bh[nt2], bH + off);
                ldm_x4(bl[nt2], bL + off);
            }
            #pragma unroll
            for (int mt = 0; mt < 2; mt++)
                #pragma unroll
                for (int nt = 0; nt < 4; nt++) {
                    uint32_t bh0 = bh[nt >> 1][(nt & 1) * 2];
                    uint32_t bh1 = bh[nt >> 1][(nt & 1) * 2 + 1];
                    uint32_t bl0 = bl[nt >> 1][(nt & 1) * 2];
                    uint32_t bl1 = bl[nt >> 1][(nt & 1) * 2 + 1];
                    mma16816(acc[mt][nt], ah[mt], bh0, bh1);
                    mma16816(acc[mt][nt], ah[mt], bl0, bl1);
                    mma16816(acc[mt][nt], al[mt], bh0, bh1);
                }
        }

        if (nxt < nch) stageA(buf ^ 1);
        asm volatile("cp.async.wait_group 0;" ::: "memory");
        __syncthreads();
        buf ^= 1;
    }

    // ---- epilogue ----
    int qr = lane >> 2;
    int qc = (lane & 3) * 2;
    #pragma unroll
    for (int mt = 0; mt < 2; mt++) {
        #pragma unroll
        for (int nt = 0; nt < 4; nt++) {
            int gm = row0 + wy * 32 + mt * 16 + qr;
            int gc = col0 + wx * 32 + nt * 8 + qc;
            float* c = acc[mt][nt];
            if (gc < N) {
                float b0 = bias[gc], b1 = bias[gc + 1];
                *(float2*)(Cf + (size_t)gm * N + gc)       = make_float2(c[0] + b0, c[1] + b1);
                *(float2*)(Cf + (size_t)(gm + 8) * N + gc) = make_float2(c[2] + b0, c[3] + b1);
            }
        }
    }
}

// ---------------- LayerNorm over last dim (512), in place -------------------
__global__ __launch_bounds__(128) void ln_kernel(
    float* __restrict__ h, const float* __restrict__ g, const float* __restrict__ b)
{
    int row = blockIdx.x;
    float4* hp = (float4*)(h + (size_t)row * LATENT);
    int t = threadIdx.x;
    float4 v = hp[t];
    float s  = v.x + v.y + v.z + v.w;
    float sq = v.x*v.x + v.y*v.y + v.z*v.z + v.w*v.w;
    #pragma unroll
    for (int o = 16; o; o >>= 1) {
        s  += __shfl_xor_sync(0xffffffffu, s, o);
        sq += __shfl_xor_sync(0xffffffffu, sq, o);
    }
    __shared__ float rs[4], rq[4];
    int lane = t & 31, wid = t >> 5;
    if (lane == 0) { rs[wid] = s; rq[wid] = sq; }
    __syncthreads();
    float S  = rs[0]+rs[1]+rs[2]+rs[3];
    float SQ = rq[0]+rq[1]+rq[2]+rq[3];
    float mu  = S * (1.0f / LATENT);
    float var = SQ * (1.0f / LATENT) - mu * mu;
    float r = rsqrtf(var + 1e-5f);
    float4 gv = ((const float4*)g)[t];
    float4 bv = ((const float4*)b)[t];
    v.x = (v.x - mu) * r * gv.x + bv.x;
    v.y = (v.y - mu) * r * gv.y + bv.y;
    v.z = (v.z - mu) * r * gv.z + bv.z;
    v.w = (v.w - mu) * r * gv.w + bv.w;
    hp[t] = v;
}

// ---------------- Oja update: one block per (b,h), cooperative softmax ------
__global__ __launch_bounds__(128) void oja_kernel(
    const float* __restrict__ kvb, const float* __restrict__ W, float* __restrict__ out)
{
    int bh = blockIdx.x;
    const float* w = W   + (size_t)bh * (D * D);
    float*       o = out + (size_t)bh * (D * D);
    const float* kv = kvb + (size_t)(bh >> 3) * KVB_N + (size_t)(bh & 7) * (2 * D + 1);

    __shared__ float Ws[D * D];
    __shared__ float vs[D], ksc[D];
    __shared__ float wmax[4], wsum[4];
    int t = threadIdx.x;
    int wid = t >> 5, lane = t & 31;

    #pragma unroll
    for (int i = t; i < (D * D) / 4; i += 128)
        ((float4*)Ws)[i] = ((const float4*)w)[i];
    if (t < D) vs[t] = tanhf(kv[D + t]);
    __syncthreads();

    float logit = -1e30f;
    if (t < D) {
        float acc = 0.f;
        #pragma unroll 16
        for (int d = 0; d < D; d++)
            acc = fmaf(Ws[d * D + t], vs[d], acc);
        logit = kv[t] - acc;
    }
    float m = logit;
    #pragma unroll
    for (int s2 = 16; s2; s2 >>= 1) m = fmaxf(m, __shfl_xor_sync(0xffffffffu, m, s2));
    if (lane == 0) wmax[wid] = m;
    __syncthreads();
    float mm = fmaxf(wmax[0], wmax[1]);

    float e = 0.f, s = 0.f;
    if (t < D) { e = expf(logit - mm); s = e; }
    #pragma unroll
    for (int s2 = 16; s2; s2 >>= 1) s += __shfl_xor_sync(0xffffffffu, s, s2);
    if (lane == 0) wsum[wid] = s;
    __syncthreads();
    float ss = wsum[0] + wsum[1];

    if (t < D) {
        float lr = 1.0f / (1.0f + expf(-kv[2 * D]));
        ksc[t] = e * (lr / ss);
    }
    __syncthreads();

    #pragma unroll
    for (int i = t; i < (D * D) / 4; i += 128) {
        float4 wv = ((const float4*)Ws)[i];
        int d  = i >> 4;
        int e0 = (i * 4) & (D - 1);
        float vd = vs[d];
        float4 r;
        r.x = fmaf(vd, ksc[e0 + 0], wv.x);
        r.y = fmaf(vd, ksc[e0 + 1], wv.y);
        r.z = fmaf(vd, ksc[e0 + 2], wv.z);
        r.w = fmaf(vd, ksc[e0 + 3], wv.w);
        ((float4*)o)[i] = r;
    }
}

// ---------------- launch -----------------------------------------------------
extern "C" void kernel_launch(void* const* d_in, const int* in_sizes, int n_in,
                              void* d_out, int out_size)
{
    const float* x     = (const float*)d_in[0];
    const float* z     = (const float*)d_in[1];
    const float* W     = (const float*)d_in[2];
    const float* ip_w  = (const float*)d_in[3];
    const float* ip_b  = (const float*)d_in[4];
    const float* ln_g  = (const float*)d_in[5];
    const float* ln_b  = (const float*)d_in[6];
    const float* mg_w  = (const float*)d_in[7];
    const float* mg_b  = (const float*)d_in[8];
    const float* kvb_w = (const float*)d_in[9];
    const float* kvb_b = (const float*)d_in[10];
    float* out = (float*)d_out;

    float *hP, *h2P, *kvbP;
    __nv_bfloat16 *ipwhi,*ipwlo,*mgwhi,*mgwlo,*kvbwhi,*kvbwlo;
    cudaGetSymbolAddress((void**)&hP,    g_h);
    cudaGetSymbolAddress((void**)&h2P,   g_h2);
    cudaGetSymbolAddress((void**)&kvbP,  g_kvb);
    cudaGetSymbolAddress((void**)&ipwhi, g_ipwT_hi);  cudaGetSymbolAddress((void**)&ipwlo, g_ipwT_lo);
    cudaGetSymbolAddress((void**)&mgwhi, g_mgwT_hi);  cudaGetSymbolAddress((void**)&mgwlo, g_mgwT_lo);
    cudaGetSymbolAddress((void**)&kvbwhi,g_kvbwT_hi); cudaGetSymbolAddress((void**)&kvbwlo,g_kvbwT_lo);

    cudaFuncSetAttribute(gemm_mma<false>,
                         cudaFuncAttributeMaxDynamicSharedMemorySize, SMEM_TOT);
    cudaFuncSetAttribute(gemm_mma<true>,
                         cudaFuncAttributeMaxDynamicSharedMemorySize, SMEM_TOT);

    // weight transpose + split (coalesced, tiled)
    tsplit_tiled<<<dim3(512/32, 512/32),  256>>>(ip_w,  ipwhi,  ipwlo,  512, 512);
    tsplit_tiled<<<dim3(1024/32, 512/32), 256>>>(mg_w,  mgwhi,  mgwlo,  1024, 512);
    tsplit_tiled<<<dim3(512/32, (KVB_N+31)/32), 256>>>(kvb_w, kvbwhi, kvbwlo, 512, KVB_N);

    // GEMM1: h = x @ ip_w + ip_b   (N=512, K=512)
    gemm_mma<false><<<dim3(8, 32), 256, SMEM_TOT>>>(
        x, nullptr, ipwhi, ipwlo, ip_b, hP, 512, 512);

    // LayerNorm in place
    ln_kernel<<<B, 128>>>(hP, ln_g, ln_b);

    // GEMM2: h2 = [h, z] @ mg_w + mg_b  (N=512, K=1024)
    gemm_mma<true><<<dim3(8, 32), 256, SMEM_TOT>>>(
        hP, z, mgwhi, mgwlo, mg_b, h2P, 512, 1024);

    // GEMM3: kvb = h2 @ kvb_w + kvb_b  (N=1032, K=512)
    gemm_mma<false><<<dim3((KVB_N + 63) / 64, 32), 256, SMEM_TOT>>>(
        h2P, nullptr, kvbwhi, kvbwlo, kvb_b, kvbP, KVB_N, 512);

    // Oja update
    oja_kernel<<<B * H, 128>>>(kvbP, W, out);
}